// round 3
// baseline (speedup 1.0000x reference)
#include <cuda_runtime.h>
#include <stdint.h>

// CTC batch loss, prob-domain forward with lazy *biased* power-of-2 rescaling.
// 2 warps per CTA, each warp owns one batch element (distinct SMSPs -> full issue rate).
// Thread ln owns states [8*ln, 8*ln+8) (lane 31 also owns state 256).
// Probability rows staged gmem->smem via per-warp cp.async ring (16 stages).

namespace {
constexpr int kB = 256, kT = 512, kC = 256, kL = 128;
constexpr int kBlank = kC - 1;          // 255
constexpr float kEps = 1e-7f;
constexpr int kWarps = 2;               // batch elements per CTA
constexpr int kDepth = 16;              // smem ring stages per warp (power of 2)
constexpr int kPF = 15;                 // prefetch distance = kDepth - 1

__device__ __forceinline__ void cp_async16(uint32_t saddr, const float* g) {
    asm volatile("cp.async.cg.shared.global [%0], [%1], 16;" :: "r"(saddr), "l"(g));
}
__device__ __forceinline__ void cp_commit() {
    asm volatile("cp.async.commit_group;" ::: "memory");
}
template <int N>
__device__ __forceinline__ void cp_wait() {
    asm volatile("cp.async.wait_group %0;" :: "n"(N) : "memory");
}
__device__ __forceinline__ uint32_t redux_max_u32(uint32_t v) {
    uint32_t r;
    asm volatile("redux.sync.max.u32 %0, %1, 0xffffffff;" : "=r"(r) : "r"(v));
    return r;
}
} // namespace

__global__ void __launch_bounds__(kWarps * 32) ctc_loss_kernel(
    const int* __restrict__ y_true,     // [B, L] int32, values in [0, C-2]
    const float* __restrict__ y_pred,   // [B, T, C] float32 probabilities
    float* __restrict__ out)            // [B] float32 loss
{
    __shared__ __align__(16) float ring[kWarps][kDepth][kC];

    const int w  = threadIdx.x >> 5;            // warp within CTA -> SMSP w
    const int ln = threadIdx.x & 31;
    const int b  = blockIdx.x * kWarps + w;     // batch element

    // --- labels owned by this thread: label indices 4*ln .. 4*ln+3 ---
    const int4 lab4 = reinterpret_cast<const int4*>(y_true + (size_t)b * kL)[ln];
    const int lab0 = lab4.x, lab1 = lab4.y, lab2 = lab4.z, lab3 = lab4.w;
    const int labm1 = __shfl_up_sync(0xffffffffu, lab3, 1);  // label 4*ln-1 (junk on lane 0)

    // skip[s] for odd s = 2k+1: allowed iff k>=1 and label[k] != label[k-1]
    const float sk0 = (ln > 0 && lab0 != labm1) ? 1.f : 0.f;
    const float sk1 = (lab1 != lab0) ? 1.f : 0.f;
    const float sk2 = (lab2 != lab1) ? 1.f : 0.f;
    const float sk3 = (lab3 != lab2) ? 1.f : 0.f;

    // --- cp.async staging: lane ln copies bytes [32*ln, 32*ln+32) of each 1KB row ---
    const float*   gbase = y_pred + (size_t)b * kT * kC + ln * 8;
    const uint32_t sbase = (uint32_t)__cvta_generic_to_shared(&ring[w][0][0]) + (uint32_t)ln * 32u;

    // prologue: rows 0..kPF-1 (one commit group per row)
    for (int r = 0; r < kPF; r++) {
        uint32_t sa = sbase + (uint32_t)(r & (kDepth - 1)) * (kC * 4);
        const float* ga = gbase + (size_t)r * kC;
        cp_async16(sa, ga);
        cp_async16(sa + 16, ga + 4);
        cp_commit();
    }

    // alpha regs: a0..a7 = states 8*ln..8*ln+7 ; a8 = state 256 (real only on lane 31)
    float a0 = 0.f, a1 = 0.f, a2 = 0.f, a3 = 0.f, a4 = 0.f,
          a5 = 0.f, a6 = 0.f, a7 = 0.f, a8 = 0.f;
    int   E = 0;                // applied base-2 exponent: true_alpha = stored * 2^E
    int   pendE = 0;            // lazily-applied rescale (measured one block earlier)
    float pendSc = 1.f;

    // current-step probs and next-step (prefetched) probs
    float pb, p1, p3, p5, p7;
    float nb, q1, q3, q5, q7;

    auto issue_row = [&](int r) {
        if (r < kT) {
            uint32_t sa = sbase + (uint32_t)(r & (kDepth - 1)) * (kC * 4);
            const float* ga = gbase + (size_t)r * kC;
            cp_async16(sa, ga);
            cp_async16(sa + 16, ga + 4);
        }
        cp_commit();  // always commit so the wait_group count stays invariant
    };
    auto load_row = [&](int t) {  // gather row t's probs into next regs
        cp_wait<kPF - 1>();
        __syncthreads();          // canonical cp.async cross-thread visibility (nw=2: ~7 cyc)
        const float* row = ring[w][t & (kDepth - 1)];
        nb = row[kBlank] + kEps;
        q1 = row[lab0]   + kEps;
        q3 = row[lab1]   + kEps;
        q5 = row[lab2]   + kEps;
        q7 = row[lab3]   + kEps;
    };
    auto advance = [&]() { pb = nb; p1 = q1; p3 = q3; p5 = q5; p7 = q7; };

    auto recur = [&]() {
        float h1 = __shfl_up_sync(0xffffffffu, a7, 1);  // alpha[8*ln - 1]
        if (ln == 0) h1 = 0.f;
        float t0 = (a0 + h1) * pb;
        float t1 = (a1 + fmaf(sk0, h1, a0)) * p1;
        float t2 = (a2 + a1) * pb;
        float t3 = (a3 + fmaf(sk1, a1, a2)) * p3;
        float t4 = (a4 + a3) * pb;
        float t5 = (a5 + fmaf(sk2, a3, a4)) * p5;
        float t6 = (a6 + a5) * pb;
        float t7 = (a7 + fmaf(sk3, a5, a6)) * p7;
        float t8 = (a8 + a7) * pb;       // state 256 (bounded junk on lanes < 31)
        a0 = t0; a1 = t1; a2 = t2; a3 = t3; a4 = t4;
        a5 = t5; a6 = t6; a7 = t7; a8 = t8;
    };

    auto do_step = [&](int t, bool load_next) {
        issue_row(t + kPF);
        if (load_next) load_row(t + 1);   // prefetch: latency covered by recur below
        recur();
        if (load_next) advance();
    };

    // Lazy biased rescale: apply last block's scale (which puts that block's measured
    // max at 2^100 -> ~226 binades of downward headroom for the 8-step lag+window,
    // while growth <= 3x/step keeps max <= 2^113), then measure a new warp max.
    auto rescale = [&]() {
        a0 *= pendSc; a1 *= pendSc; a2 *= pendSc; a3 *= pendSc; a4 *= pendSc;
        a5 *= pendSc; a6 *= pendSc; a7 *= pendSc; a8 *= pendSc;
        E += pendE;
        float m = fmaxf(fmaxf(fmaxf(a0, a1), fmaxf(a2, a3)),
                        fmaxf(fmaxf(a4, a5), fmaxf(a6, fmaxf(a7, a8))));
        uint32_t mm = redux_max_u32(__float_as_uint(m));   // positive fp32: u32 order-preserving
        int eb   = (int)(mm >> 23);                        // biased exponent of warp max
        int sexp = 227 - eb;                               // scale so max -> 2^100
        if (sexp > 127) sexp = 127;                        // keep encodable (eb >= 0 => sexp >= -27)
        pendSc = __int_as_float((uint32_t)(sexp + 127) << 23);  // 2^sexp
        pendE  = -sexp;
    };

    // ---- t = 0 : init ----
    cp_wait<kPF - 1>();
    __syncthreads();
    {
        const float* row = ring[w][0];
        pb = row[kBlank] + kEps;
        p1 = row[lab0]   + kEps;
    }
    issue_row(kPF);
    load_row(1);
    if (ln == 0) { a0 = pb; a1 = p1; }    // only states 0 and 1 reachable at t=0
    advance();

    do_step(1, true);
    do_step(2, true);
    do_step(3, true);

#pragma unroll 1
    for (int base = 4; base < 508; base += 4) {
        rescale();
        do_step(base,     true);
        do_step(base + 1, true);
        do_step(base + 2, true);
        do_step(base + 3, true);
    }
    rescale();
    do_step(508, true);
    do_step(509, true);
    do_step(510, true);
    do_step(511, false);

    // loss = -log(alpha[S-1] + alpha[S-2]); states 256 and 255 live on lane 31.
    // pendSc is intentionally unapplied: alphas are still in the E-scaled frame.
    if (ln == 31) {
        float tot = a8 + a7;
        out[b] = -(logf(tot) + (float)E * 0.6931471805599453f);
    }
}

extern "C" void kernel_launch(void* const* d_in, const int* in_sizes, int n_in,
                              void* d_out, int out_size) {
    const int* y_true;
    const float* y_pred;
    if (in_sizes[0] == kB * kL) {
        y_true = (const int*)d_in[0];
        y_pred = (const float*)d_in[1];
    } else {
        y_true = (const int*)d_in[1];
        y_pred = (const float*)d_in[0];
    }
    (void)n_in; (void)out_size;
    ctc_loss_kernel<<<kB / kWarps, kWarps * 32>>>(y_true, y_pred, (float*)d_out);
}

// round 4
// speedup vs baseline: 1.2108x; 1.2108x over previous
#include <cuda_runtime.h>
#include <stdint.h>

// CTC batch loss, prob-domain forward with lazy biased power-of-2 rescaling.
// One warp per batch element (grid=256, block=32). Thread ln owns states
// [8*ln, 8*ln+8) (lane 31 also owns state 256).
// Time loop blocked by 4: probability rows staged gmem->smem via cp.async in
// 4-row commit groups (32-row ring, 7 groups in flight); one wait+barrier and
// one batch of 20 gathered LDS per 4 recurrence steps.

namespace {
constexpr int kB = 256, kT = 512, kC = 256, kL = 128;
constexpr int kBlank = kC - 1;          // 255
constexpr float kEps = 1e-7f;
constexpr int kDepth = 32;              // smem ring rows (power of 2)
constexpr int kGroup = 4;               // rows per commit group = steps per block
constexpr int kNG    = kT / kGroup;     // 128 groups
constexpr int kPFG   = 7;               // commit groups kept in flight (28 rows)

__device__ __forceinline__ void cp_async16(uint32_t saddr, const float* g) {
    asm volatile("cp.async.cg.shared.global [%0], [%1], 16;" :: "r"(saddr), "l"(g));
}
__device__ __forceinline__ void cp_commit() {
    asm volatile("cp.async.commit_group;" ::: "memory");
}
template <int N>
__device__ __forceinline__ void cp_wait() {
    asm volatile("cp.async.wait_group %0;" :: "n"(N) : "memory");
}
__device__ __forceinline__ uint32_t redux_max_u32(uint32_t v) {
    uint32_t r;
    asm volatile("redux.sync.max.u32 %0, %1, 0xffffffff;" : "=r"(r) : "r"(v));
    return r;
}
} // namespace

__global__ void __launch_bounds__(32) ctc_loss_kernel(
    const int* __restrict__ y_true,     // [B, L] int32, values in [0, C-2]
    const float* __restrict__ y_pred,   // [B, T, C] float32 probabilities
    float* __restrict__ out)            // [B] float32 loss
{
    __shared__ __align__(16) float ring[kDepth][kC];   // 32 KB

    const int b  = blockIdx.x;
    const int ln = threadIdx.x;

    // --- labels owned by this thread: label indices 4*ln .. 4*ln+3 ---
    const int4 lab4 = reinterpret_cast<const int4*>(y_true + (size_t)b * kL)[ln];
    const int lab0 = lab4.x, lab1 = lab4.y, lab2 = lab4.z, lab3 = lab4.w;
    const int labm1 = __shfl_up_sync(0xffffffffu, lab3, 1);  // label 4*ln-1 (junk on lane 0)

    // skip[s] for odd s = 2k+1: allowed iff k>=1 and label[k] != label[k-1]
    const float sk0 = (ln > 0 && lab0 != labm1) ? 1.f : 0.f;
    const float sk1 = (lab1 != lab0) ? 1.f : 0.f;
    const float sk2 = (lab2 != lab1) ? 1.f : 0.f;
    const float sk3 = (lab3 != lab2) ? 1.f : 0.f;

    // --- cp.async staging: lane ln copies bytes [32*ln, 32*ln+32) of each 1KB row ---
    const float*   gbase = y_pred + (size_t)b * kT * kC + ln * 8;
    const uint32_t sbase = (uint32_t)__cvta_generic_to_shared(&ring[0][0]) + (uint32_t)ln * 32u;

    auto issue_group = [&](int g) {     // 4 rows per commit group
        if (g < kNG) {
#pragma unroll
            for (int j = 0; j < kGroup; j++) {
                int r = g * kGroup + j;
                uint32_t sa = sbase + (uint32_t)(r & (kDepth - 1)) * (kC * 4);
                const float* ga = gbase + (size_t)r * kC;
                cp_async16(sa, ga);
                cp_async16(sa + 16, ga + 4);
            }
        }
        cp_commit();                    // always commit: wait_group count invariant
    };

    // prologue: groups 0..kPFG-1 (rows 0..27)
    for (int g = 0; g < kPFG; g++) issue_group(g);

    // alpha regs: a0..a7 = states 8*ln..8*ln+7 ; a8 = state 256 (real only on lane 31)
    float a0 = 0.f, a1 = 0.f, a2 = 0.f, a3 = 0.f, a4 = 0.f,
          a5 = 0.f, a6 = 0.f, a7 = 0.f, a8 = 0.f;
    int   E = 0;                // applied base-2 exponent: true_alpha = stored * 2^E
    int   pendE = 0;            // lazily-applied rescale (measured one block earlier)
    float pendSc = 1.f;

    float P[kGroup][5];         // gathered probs for the 4 rows of the current block

    auto gather = [&](int t_base) {     // 20 LDS, fully unrolled -> registers
#pragma unroll
        for (int j = 0; j < kGroup; j++) {
            const float* row = ring[(t_base + j) & (kDepth - 1)];
            P[j][0] = row[kBlank] + kEps;
            P[j][1] = row[lab0]   + kEps;
            P[j][2] = row[lab1]   + kEps;
            P[j][3] = row[lab2]   + kEps;
            P[j][4] = row[lab3]   + kEps;
        }
    };

    auto recur = [&](float pb, float p1, float p3, float p5, float p7) {
        float h1 = __shfl_up_sync(0xffffffffu, a7, 1);  // alpha[8*ln - 1]
        if (ln == 0) h1 = 0.f;
        float t0 = (a0 + h1) * pb;
        float t1 = (a1 + fmaf(sk0, h1, a0)) * p1;
        float t2 = (a2 + a1) * pb;
        float t3 = (a3 + fmaf(sk1, a1, a2)) * p3;
        float t4 = (a4 + a3) * pb;
        float t5 = (a5 + fmaf(sk2, a3, a4)) * p5;
        float t6 = (a6 + a5) * pb;
        float t7 = (a7 + fmaf(sk3, a5, a6)) * p7;
        float t8 = (a8 + a7) * pb;       // state 256 (bounded junk on lanes < 31)
        a0 = t0; a1 = t1; a2 = t2; a3 = t3; a4 = t4;
        a5 = t5; a6 = t6; a7 = t7; a8 = t8;
    };

    // Lazy biased rescale: apply last block's scale (puts that block's measured max
    // at 2^100 -> ~226 binades of downward headroom over the 8-step lag+window,
    // while growth <= 3x/step keeps the max <= ~2^113), then measure a new warp max.
    auto rescale = [&]() {
        a0 *= pendSc; a1 *= pendSc; a2 *= pendSc; a3 *= pendSc; a4 *= pendSc;
        a5 *= pendSc; a6 *= pendSc; a7 *= pendSc; a8 *= pendSc;
        E += pendE;
        float m = fmaxf(fmaxf(fmaxf(a0, a1), fmaxf(a2, a3)),
                        fmaxf(fmaxf(a4, a5), fmaxf(a6, fmaxf(a7, a8))));
        uint32_t mm = redux_max_u32(__float_as_uint(m));   // positive fp32: u32 order-preserving
        int eb   = (int)(mm >> 23);                        // biased exponent of warp max
        int sexp = 227 - eb;                               // scale so max -> 2^100
        if (sexp > 127) sexp = 127;                        // keep encodable
        pendSc = __int_as_float((uint32_t)(sexp + 127) << 23);  // 2^sexp
        pendE  = -sexp;
    };

    // ---- block 0: t = 0 (init) and t = 1..3 ----
    cp_wait<kPFG - 1>();
    __syncthreads();
    gather(0);
    if (ln == 0) { a0 = P[0][0]; a1 = P[0][1]; }   // only states 0,1 reachable at t=0
    recur(P[1][0], P[1][1], P[1][2], P[1][3], P[1][4]);
    recur(P[2][0], P[2][1], P[2][2], P[2][3], P[2][4]);
    recur(P[3][0], P[3][1], P[3][2], P[3][3], P[3][4]);
    issue_group(kPFG);

    // ---- blocks 1..127: 4 steps each ----
#pragma unroll 1
    for (int g = 1; g < kNG; g++) {
        rescale();                       // register math; overlaps any wait stall below
        cp_wait<kPFG - 1>();             // group g resident (committed = g+7, <=6 pending)
        __syncthreads();                 // cp.async cross-lane visibility (nw=1: ~3 cyc)
        gather(g * kGroup);
        recur(P[0][0], P[0][1], P[0][2], P[0][3], P[0][4]);
        recur(P[1][0], P[1][1], P[1][2], P[1][3], P[1][4]);
        recur(P[2][0], P[2][1], P[2][2], P[2][3], P[2][4]);
        recur(P[3][0], P[3][1], P[3][2], P[3][3], P[3][4]);
        issue_group(g + kPFG);
    }

    // loss = -log(alpha[S-1] + alpha[S-2]); states 256 and 255 live on lane 31.
    // pendSc intentionally unapplied: alphas are still in the E-scaled frame.
    if (ln == 31) {
        float tot = a8 + a7;
        out[b] = -(logf(tot) + (float)E * 0.6931471805599453f);
    }
}

extern "C" void kernel_launch(void* const* d_in, const int* in_sizes, int n_in,
                              void* d_out, int out_size) {
    const int* y_true;
    const float* y_pred;
    if (in_sizes[0] == kB * kL) {
        y_true = (const int*)d_in[0];
        y_pred = (const float*)d_in[1];
    } else {
        y_true = (const int*)d_in[1];
        y_pred = (const float*)d_in[0];
    }
    (void)n_in; (void)out_size;
    ctc_loss_kernel<<<kB, 32>>>(y_true, y_pred, (float*)d_out);
}